// round 7
// baseline (speedup 1.0000x reference)
#include <cuda_runtime.h>
#include <cuda_bf16.h>
#include <cstdint>

// ---------------------------------------------------------------------------
// Problem dims
// ---------------------------------------------------------------------------
#define N_DIM  8192
#define IN_CH  128
#define OUT_CH 64

// Big-GEMM tiling (mma.sync bf16; tcgen05 not available at compute_103)
#define TM       128               // M rows per CTA
#define KB       64                // K per stage (bf16 elements)
#define SPLITK   8
#define KSPAN    (N_DIM / SPLITK)  // 1024
#define NITER    (KSPAN / KB)      // 16
#define GTHREADS 256               // 8 warps; each warp: 16 rows x 64 cols

// Static SMEM: 128B rows, XOR chunk swizzle (16B chunks: c ^= r&7) -> no pad
#define S_AH     0                 // 128 rows * 128 B = 16384
#define S_AL     16384
#define S_BH     32768             // 64 rows * 128 B  =  8192
#define S_BL     40960
#define S_TOTAL  49152             // exactly the 48 KB static limit

// ---------------------------------------------------------------------------
// Scratch (__device__ globals: allocation-free rule). Referenced ONLY from
// device code — never passed as kernel args from host (R4/R5 bug).
// ---------------------------------------------------------------------------
__device__ __align__(16) float g_tr[N_DIM * OUT_CH];             // features @ W
__device__ __align__(16) float g_sp[N_DIM * OUT_CH];             // filt * (Winv @ g_tr)
__device__ __align__(16) float g_part[SPLITK * N_DIM * OUT_CH];  // split-K partials
__device__ __align__(16) __nv_bfloat16 g_bh[OUT_CH * N_DIM];     // B^T hi, K-major [64][8192]
__device__ __align__(16) __nv_bfloat16 g_bl[OUT_CH * N_DIM];     // B^T lo

// ---------------------------------------------------------------------------
// PTX helpers (baseline ISA: ldmatrix + mma.sync only)
// ---------------------------------------------------------------------------
__device__ __forceinline__ uint32_t smem_u32(const void* p) {
    uint32_t a;
    asm("{ .reg .u64 t; cvta.to.shared.u64 t, %1; cvt.u32.u64 %0, t; }"
        : "=r"(a) : "l"(p));
    return a;
}
__device__ __forceinline__ void ldsm4(uint32_t* r, uint32_t addr) {
    asm volatile("ldmatrix.sync.aligned.m8n8.x4.shared.b16 {%0,%1,%2,%3}, [%4];"
                 : "=r"(r[0]), "=r"(r[1]), "=r"(r[2]), "=r"(r[3]) : "r"(addr));
}
__device__ __forceinline__ void mma16816(float* c, const uint32_t* a,
                                         uint32_t b0, uint32_t b1) {
    asm volatile(
        "mma.sync.aligned.m16n8k16.row.col.f32.bf16.bf16.f32 "
        "{%0,%1,%2,%3}, {%4,%5,%6,%7}, {%8,%9}, {%0,%1,%2,%3};"
        : "+f"(c[0]), "+f"(c[1]), "+f"(c[2]), "+f"(c[3])
        : "r"(a[0]), "r"(a[1]), "r"(a[2]), "r"(a[3]), "r"(b0), "r"(b1));
}

// ---------------------------------------------------------------------------
// Kernel 1: g_tr = features @ W      [8192,128] @ [128,64]   (R2/R6-proven)
// ---------------------------------------------------------------------------
__global__ __launch_bounds__(256) void lin_kernel(
    const float* __restrict__ F, const float* __restrict__ W)
{
    __shared__ float Ws[IN_CH][OUT_CH];
    const int tid = threadIdx.x;
    #pragma unroll
    for (int t = 0; t < 8; t++) {
        int idx = tid + t * 256;
        int r = idx >> 4, c4 = idx & 15;
        *reinterpret_cast<float4*>(&Ws[r][c4 * 4]) =
            *reinterpret_cast<const float4*>(&W[r * OUT_CH + c4 * 4]);
    }
    __syncthreads();

    const int row = blockIdx.x * 32 + (tid >> 3);
    const int c0  = (tid & 7) * 8;
    float acc[8];
    #pragma unroll
    for (int j = 0; j < 8; j++) acc[j] = 0.0f;

    #pragma unroll 8
    for (int k = 0; k < IN_CH; k += 4) {
        float4 a4 = *reinterpret_cast<const float4*>(&F[row * IN_CH + k]);
        float av[4] = {a4.x, a4.y, a4.z, a4.w};
        #pragma unroll
        for (int kk = 0; kk < 4; kk++)
            #pragma unroll
            for (int j = 0; j < 8; j++)
                acc[j] = fmaf(av[kk], Ws[k + kk][c0 + j], acc[j]);
    }
    #pragma unroll
    for (int j = 0; j < 8; j++) g_tr[row * OUT_CH + c0 + j] = acc[j];
}

// ---------------------------------------------------------------------------
// Kernel 2: split src[K,64] fp32 -> transposed K-major bf16 hi/lo.
//   which=0: src = g_tr ;  which=1: src = g_sp   (selected IN DEVICE CODE)
// ---------------------------------------------------------------------------
__global__ __launch_bounds__(256) void prep_b(int which)
{
    const float* __restrict__ src = which ? g_sp : g_tr;
    int idx = blockIdx.x * 256 + threadIdx.x;       // = n*8192 + k
    int k = idx & (N_DIM - 1);
    int n = idx >> 13;
    float v = src[k * OUT_CH + n];
    uint32_t u = __float_as_uint(v);
    float hi = __uint_as_float(u & 0xFFFF0000u);
    float lo = v - hi;
    reinterpret_cast<unsigned short*>(g_bh)[idx] = (unsigned short)(u >> 16);
    g_bl[idx] = __float2bfloat16(lo);
}

// ---------------------------------------------------------------------------
// Kernel 3: bf16-split GEMM (mma.sync.m16n8k16), KB=64, XOR-swizzled SMEM.
//   partial[s] = A[mTile, kspan_s] @ B^T ;  D = Ah*Bh + Ah*Bl + Al*Bh
// ---------------------------------------------------------------------------

// A: per thread 8 float4 (row aR, cols aH*32..+31); B: 4 uint4.
#define LDG_TILE(it_) do {                                                      \
    _Pragma("unroll")                                                           \
    for (int j_ = 0; j_ < 8; j_++)                                              \
        stA[j_] = *reinterpret_cast<const float4*>(                             \
            Ablk + (size_t)aR * N_DIM + (it_) * KB + aH * 32 + j_ * 4);         \
    _Pragma("unroll")                                                           \
    for (int i_ = 0; i_ < 4; i_++) {                                            \
        int idx_ = tid + i_ * GTHREADS;        /* 0..1023 */                    \
        int rem_ = idx_ & 511, row_ = rem_ >> 3, c_ = rem_ & 7;                 \
        const __nv_bfloat16* src_ = (idx_ >> 9) ? g_bl : g_bh;                  \
        stB[i_] = *reinterpret_cast<const uint4*>(                              \
            src_ + (size_t)row_ * N_DIM + kBase + (it_) * KB + c_ * 8);         \
    }                                                                           \
} while (0)

// Convert staged regs, store swizzled: chunk i -> byte r*128 + ((c^(r&7))*16)
#define STS_TILE() do {                                                         \
    _Pragma("unroll")                                                           \
    for (int i_ = 0; i_ < 4; i_++) {       /* 16B chunk = 2 float4 */           \
        float4 va_ = stA[i_ * 2], vb_ = stA[i_ * 2 + 1];                        \
        uint32_t u0_ = __float_as_uint(va_.x), u1_ = __float_as_uint(va_.y);    \
        uint32_t u2_ = __float_as_uint(va_.z), u3_ = __float_as_uint(va_.w);    \
        uint32_t u4_ = __float_as_uint(vb_.x), u5_ = __float_as_uint(vb_.y);    \
        uint32_t u6_ = __float_as_uint(vb_.z), u7_ = __float_as_uint(vb_.w);    \
        uint4 h_, l_;                                                           \
        asm("prmt.b32 %0, %1, %2, 0x7632;" : "=r"(h_.x) : "r"(u0_), "r"(u1_));  \
        asm("prmt.b32 %0, %1, %2, 0x7632;" : "=r"(h_.y) : "r"(u2_), "r"(u3_));  \
        asm("prmt.b32 %0, %1, %2, 0x7632;" : "=r"(h_.z) : "r"(u4_), "r"(u5_));  \
        asm("prmt.b32 %0, %1, %2, 0x7632;" : "=r"(h_.w) : "r"(u6_), "r"(u7_));  \
        float f0_ = va_.x - __uint_as_float(u0_ & 0xFFFF0000u);                 \
        float f1_ = va_.y - __uint_as_float(u1_ & 0xFFFF0000u);                 \
        float f2_ = va_.z - __uint_as_float(u2_ & 0xFFFF0000u);                 \
        float f3_ = va_.w - __uint_as_float(u3_ & 0xFFFF0000u);                 \
        float f4_ = vb_.x - __uint_as_float(u4_ & 0xFFFF0000u);                 \
        float f5_ = vb_.y - __uint_as_float(u5_ & 0xFFFF0000u);                 \
        float f6_ = vb_.z - __uint_as_float(u6_ & 0xFFFF0000u);                 \
        float f7_ = vb_.w - __uint_as_float(u7_ & 0xFFFF0000u);                 \
        asm("cvt.rn.bf16x2.f32 %0, %1, %2;" : "=r"(l_.x) : "f"(f1_), "f"(f0_)); \
        asm("cvt.rn.bf16x2.f32 %0, %1, %2;" : "=r"(l_.y) : "f"(f3_), "f"(f2_)); \
        asm("cvt.rn.bf16x2.f32 %0, %1, %2;" : "=r"(l_.z) : "f"(f5_), "f"(f4_)); \
        asm("cvt.rn.bf16x2.f32 %0, %1, %2;" : "=r"(l_.w) : "f"(f7_), "f"(f6_)); \
        uint32_t c_   = (uint32_t)(aH * 4 + i_);                                \
        uint32_t off_ = (uint32_t)aR * 128 + (((c_ ^ aR7) & 7u) << 4);          \
        *reinterpret_cast<uint4*>(sm + S_AH + off_) = h_;                       \
        *reinterpret_cast<uint4*>(sm + S_AL + off_) = l_;                       \
    }                                                                           \
    _Pragma("unroll")                                                           \
    for (int i_ = 0; i_ < 4; i_++) {                                            \
        int idx_ = tid + i_ * GTHREADS;                                         \
        int rem_ = idx_ & 511, row_ = rem_ >> 3, c_ = rem_ & 7;                 \
        char* b_ = (idx_ >> 9) ? (sm + S_BL) : (sm + S_BH);                     \
        uint32_t off_ = (uint32_t)row_ * 128 +                                  \
                        ((uint32_t)((c_ ^ row_) & 7) << 4);                     \
        *reinterpret_cast<uint4*>(b_ + off_) = stB[i_];                         \
    }                                                                           \
} while (0)

__global__ __launch_bounds__(GTHREADS, 2) void mma_gemm(const float* __restrict__ A)
{
    __shared__ __align__(128) char sm[S_TOTAL];
    const uint32_t sbase = smem_u32(sm);

    const int tid = threadIdx.x;
    const int wid = tid >> 5;
    const int lid = tid & 31;
    const int wm  = wid * 16;                 // warp's 16-row slice

    const int mBase = blockIdx.x * TM;
    const int kBase = blockIdx.y * KSPAN;
    const float* Ablk = A + (size_t)mBase * N_DIM + kBase;

    // A staging coords: row = tid>>1, half = tid&1 -> 32 consecutive floats
    const int aR = tid >> 1;
    const int aH = tid & 1;
    const uint32_t aR7 = (uint32_t)(aR & 7);
    float4 stA[8];
    uint4  stB[4];

    float acc[8][4];
    #pragma unroll
    for (int t = 0; t < 8; t++)
        #pragma unroll
        for (int j = 0; j < 4; j++) acc[t][j] = 0.0f;

    // per-lane ldmatrix coords (chunk index XOR-swizzled per k-step)
    //   A x4: rows wm+(lid&15); chunk = ks*2 + (lid>>4)
    const uint32_t rA    = (uint32_t)(wm + (lid & 15));
    const uint32_t rAm   = rA & 7u;
    const uint32_t aRow  = sbase + S_AH + rA * 128;
    const uint32_t aSel  = (uint32_t)(lid >> 4);
    //   B x4: rows np*16 + rBL; chunk = ks*2 + bSel
    const uint32_t rBL   = (uint32_t)((lid & 7) + ((lid >> 4) & 1) * 8);
    const uint32_t bSel  = (uint32_t)((lid >> 3) & 1);

    LDG_TILE(0);

    for (int it = 0; it < NITER; it++) {
        if (it > 0) __syncthreads();          // prior compute done
        STS_TILE();
        __syncthreads();                      // stage visible
        if (it + 1 < NITER) LDG_TILE(it + 1); // LDGs fly during compute

        #pragma unroll
        for (int ks = 0; ks < 4; ks++) {
            uint32_t ah[4], al[4];
            {
                uint32_t cA = ((uint32_t)(ks * 2) + aSel) ^ rAm;
                uint32_t aAddr = aRow + (cA << 4);
                ldsm4(ah, aAddr);
                ldsm4(al, aAddr + (S_AL - S_AH));
            }
            #pragma unroll
            for (int np = 0; np < 4; np++) {
                uint32_t rB = (uint32_t)np * 16 + rBL;
                uint32_t cB = ((uint32_t)(ks * 2) + bSel) ^ (rB & 7u);
                uint32_t bAddr = sbase + S_BH + rB * 128 + (cB << 4);
                uint32_t bh[4], bl[4];
                ldsm4(bh, bAddr);
                ldsm4(bl, bAddr + (S_BL - S_BH));
                float* c0 = acc[np * 2];
                float* c1 = acc[np * 2 + 1];
                // interleave c0/c1 so same-acc MMAs are spaced
                mma16816(c0, ah, bh[0], bh[1]);
                mma16816(c1, ah, bh[2], bh[3]);
                mma16816(c0, ah, bl[0], bl[1]);
                mma16816(c1, ah, bl[2], bl[3]);
                mma16816(c0, al, bh[0], bh[1]);
                mma16816(c1, al, bh[2], bh[3]);
            }
        }
    }

    // epilogue: c-fragment (row = lid>>2 (+8), col = (lid&3)*2 (+1))
    const int g  = lid >> 2;
    const int tg = lid & 3;
    float* part = g_part + (size_t)blockIdx.y * (N_DIM * OUT_CH);
    const int row0 = mBase + wm + g;
    #pragma unroll
    for (int t = 0; t < 8; t++) {
        int col = t * 8 + tg * 2;
        *reinterpret_cast<float2*>(&part[(size_t)row0 * OUT_CH + col]) =
            make_float2(acc[t][0], acc[t][1]);
        *reinterpret_cast<float2*>(&part[(size_t)(row0 + 8) * OUT_CH + col]) =
            make_float2(acc[t][2], acc[t][3]);
    }
}

// ---------------------------------------------------------------------------
// Kernel 4: reduce split-K partials.
//   phase 0: g_sp = filt[m] * sum_s P[s]     phase 1: d_out = sum_s P[s]
// ---------------------------------------------------------------------------
__global__ __launch_bounds__(256) void reduce_kernel(
    const float* __restrict__ filt, float* __restrict__ outp, int phase)
{
    const int i = blockIdx.x * blockDim.x + threadIdx.x;
    const int stride4 = (N_DIM * OUT_CH) / 4;
    const float4* P = reinterpret_cast<const float4*>(g_part);

    float4 s = P[i];
    #pragma unroll
    for (int sp = 1; sp < SPLITK; sp++) {
        float4 v = P[i + sp * stride4];
        s.x += v.x; s.y += v.y; s.z += v.z; s.w += v.w;
    }
    if (phase == 0) {
        int m = (i * 4) / OUT_CH;
        float f = filt[m];
        s.x *= f; s.y *= f; s.z *= f; s.w *= f;
        reinterpret_cast<float4*>(g_sp)[i] = s;
    } else {
        reinterpret_cast<float4*>(outp)[i] = s;
    }
}

// ---------------------------------------------------------------------------
// Launch. Inputs: features, weight_matrix, filt, wavelets, wavelets_inv.
// No dynamic smem, no attributes, no static state, no device symbols as args.
// ---------------------------------------------------------------------------
extern "C" void kernel_launch(void* const* d_in, const int* in_sizes, int n_in,
                              void* d_out, int out_size)
{
    const float* features     = (const float*)d_in[0];
    const float* weight       = (const float*)d_in[1];
    const float* filt         = (const float*)d_in[2];
    const float* wavelets     = (const float*)d_in[3];
    const float* wavelets_inv = (const float*)d_in[4];
    float* out = (float*)d_out;

    dim3 grid(N_DIM / TM, SPLITK);                      // (64, 8)
    const int prepBlocks = (N_DIM * OUT_CH) / 256;      // 2048
    const int redBlocks  = (N_DIM * OUT_CH) / 4 / 256;  // 512

    // 1) g_tr = features @ W
    lin_kernel<<<N_DIM / 32, 256>>>(features, weight);
    // 2) split+transpose g_tr -> g_bh/g_bl
    prep_b<<<prepBlocks, 256>>>(0);
    // 3) partials = wavelets_inv @ g_tr
    mma_gemm<<<grid, GTHREADS>>>(wavelets_inv);
    // 4) g_sp = filt[:,None] * sum(partials)
    reduce_kernel<<<redBlocks, 256>>>(filt, nullptr, 0);
    // 5) split+transpose g_sp
    prep_b<<<prepBlocks, 256>>>(1);
    // 6) partials = wavelets @ g_sp
    mma_gemm<<<grid, GTHREADS>>>(wavelets);
    // 7) out = sum(partials)
    reduce_kernel<<<redBlocks, 256>>>(filt, out, 1);
}

// round 8
// speedup vs baseline: 1.2608x; 1.2608x over previous
#include <cuda_runtime.h>
#include <cuda_bf16.h>
#include <cstdint>

// ---------------------------------------------------------------------------
// Problem dims
// ---------------------------------------------------------------------------
#define N_DIM  8192
#define IN_CH  128
#define OUT_CH 64

// Big-GEMM tiling (mma.sync bf16; tcgen05 not available at compute_103)
#define TM       128               // M rows per CTA
#define KB       32                // K per stage (bf16 elements)
#define SPLITK   8
#define KSPAN    (N_DIM / SPLITK)  // 1024
#define NITER    (KSPAN / KB)      // 32
#define GTHREADS 256               // 8 warps; each warp: 16 rows x 64 cols

// Double-buffered SMEM: 64B rows, chunk swizzle c ^= (r>>1)&3 (16B chunks).
// Stage: Ah 8192 | Al 8192 | Bh 4096 | Bl 4096 = 24576 B; x2 = 49152 (48KB).
#define ST_AH    0
#define ST_AL    8192
#define ST_BH    16384
#define ST_BL    20480
#define STAGE    24576
#define S_TOTAL  49152

// ---------------------------------------------------------------------------
// Scratch (__device__ globals). Referenced ONLY from device code — never
// passed as kernel args from host (that was the R4/R5 bug).
// ---------------------------------------------------------------------------
__device__ __align__(16) float g_tr[N_DIM * OUT_CH];             // features @ W
__device__ __align__(16) float g_sp[N_DIM * OUT_CH];             // filt * (Winv @ g_tr)
__device__ __align__(16) float g_part[SPLITK * N_DIM * OUT_CH];  // split-K partials
__device__ __align__(16) __nv_bfloat16 g_bh[OUT_CH * N_DIM];     // B^T hi, K-major
__device__ __align__(16) __nv_bfloat16 g_bl[OUT_CH * N_DIM];     // B^T lo

// ---------------------------------------------------------------------------
// PTX helpers (baseline ISA: ldmatrix + mma.sync only)
// ---------------------------------------------------------------------------
__device__ __forceinline__ uint32_t smem_u32(const void* p) {
    uint32_t a;
    asm("{ .reg .u64 t; cvta.to.shared.u64 t, %1; cvt.u32.u64 %0, t; }"
        : "=r"(a) : "l"(p));
    return a;
}
__device__ __forceinline__ void ldsm4(uint32_t* r, uint32_t addr) {
    asm volatile("ldmatrix.sync.aligned.m8n8.x4.shared.b16 {%0,%1,%2,%3}, [%4];"
                 : "=r"(r[0]), "=r"(r[1]), "=r"(r[2]), "=r"(r[3]) : "r"(addr));
}
__device__ __forceinline__ void mma16816(float* c, const uint32_t* a,
                                         uint32_t b0, uint32_t b1) {
    asm volatile(
        "mma.sync.aligned.m16n8k16.row.col.f32.bf16.bf16.f32 "
        "{%0,%1,%2,%3}, {%4,%5,%6,%7}, {%8,%9}, {%0,%1,%2,%3};"
        : "+f"(c[0]), "+f"(c[1]), "+f"(c[2]), "+f"(c[3])
        : "r"(a[0]), "r"(a[1]), "r"(a[2]), "r"(a[3]), "r"(b0), "r"(b1));
}

// ---------------------------------------------------------------------------
// Kernel 1: g_tr = features @ W      [8192,128] @ [128,64]   (R2/R6-proven)
// ---------------------------------------------------------------------------
__global__ __launch_bounds__(256) void lin_kernel(
    const float* __restrict__ F, const float* __restrict__ W)
{
    __shared__ float Ws[IN_CH][OUT_CH];
    const int tid = threadIdx.x;
    #pragma unroll
    for (int t = 0; t < 8; t++) {
        int idx = tid + t * 256;
        int r = idx >> 4, c4 = idx & 15;
        *reinterpret_cast<float4*>(&Ws[r][c4 * 4]) =
            *reinterpret_cast<const float4*>(&W[r * OUT_CH + c4 * 4]);
    }
    __syncthreads();

    const int row = blockIdx.x * 32 + (tid >> 3);
    const int c0  = (tid & 7) * 8;
    float acc[8];
    #pragma unroll
    for (int j = 0; j < 8; j++) acc[j] = 0.0f;

    #pragma unroll 8
    for (int k = 0; k < IN_CH; k += 4) {
        float4 a4 = *reinterpret_cast<const float4*>(&F[row * IN_CH + k]);
        float av[4] = {a4.x, a4.y, a4.z, a4.w};
        #pragma unroll
        for (int kk = 0; kk < 4; kk++)
            #pragma unroll
            for (int j = 0; j < 8; j++)
                acc[j] = fmaf(av[kk], Ws[k + kk][c0 + j], acc[j]);
    }
    #pragma unroll
    for (int j = 0; j < 8; j++) g_tr[row * OUT_CH + c0 + j] = acc[j];
}

// ---------------------------------------------------------------------------
// Kernel 2: split src[K,64] fp32 -> transposed K-major bf16 hi/lo.
//   which=0: src = g_tr ;  which=1: src = g_sp   (selected IN DEVICE CODE)
// ---------------------------------------------------------------------------
__global__ __launch_bounds__(256) void prep_b(int which)
{
    const float* __restrict__ src = which ? g_sp : g_tr;
    int idx = blockIdx.x * 256 + threadIdx.x;       // = n*8192 + k
    int k = idx & (N_DIM - 1);
    int n = idx >> 13;
    float v = src[k * OUT_CH + n];
    uint32_t u = __float_as_uint(v);
    float hi = __uint_as_float(u & 0xFFFF0000u);
    float lo = v - hi;
    reinterpret_cast<unsigned short*>(g_bh)[idx] = (unsigned short)(u >> 16);
    g_bl[idx] = __float2bfloat16(lo);
}

// ---------------------------------------------------------------------------
// Kernel 3: bf16-split GEMM (mma.sync.m16n8k16), KB=32, DOUBLE-BUFFERED.
//   partial[s] = A[mTile, kspan_s] @ B^T ;  D = Ah*Bh + Ah*Bl + Al*Bh
// ---------------------------------------------------------------------------

// A: per thread 4 float4 (row aR, 16 floats at col aH*16); B: 1 hi + 1 lo uint4
#define LDG_TILE(it_) do {                                                      \
    _Pragma("unroll")                                                           \
    for (int j_ = 0; j_ < 4; j_++)                                              \
        stA[j_] = *reinterpret_cast<const float4*>(                             \
            Ablk + (size_t)aR * N_DIM + (it_) * KB + aH * 16 + j_ * 4);         \
    stBh = *reinterpret_cast<const uint4*>(                                     \
        g_bh + (size_t)bRow * N_DIM + kBase + (it_) * KB + bC * 8);             \
    stBl = *reinterpret_cast<const uint4*>(                                     \
        g_bl + (size_t)bRow * N_DIM + kBase + (it_) * KB + bC * 8);             \
} while (0)

// Convert + store into stage buf_ (chunk-swizzled 64B rows)
#define STS_TILE(buf_) do {                                                     \
    char* sb_ = sm + (buf_) * STAGE;                                            \
    _Pragma("unroll")                                                           \
    for (int i_ = 0; i_ < 2; i_++) {       /* 16B chunk from 8 floats */        \
        float4 va_ = stA[i_ * 2], vb_ = stA[i_ * 2 + 1];                        \
        uint32_t u0_ = __float_as_uint(va_.x), u1_ = __float_as_uint(va_.y);    \
        uint32_t u2_ = __float_as_uint(va_.z), u3_ = __float_as_uint(va_.w);    \
        uint32_t u4_ = __float_as_uint(vb_.x), u5_ = __float_as_uint(vb_.y);    \
        uint32_t u6_ = __float_as_uint(vb_.z), u7_ = __float_as_uint(vb_.w);    \
        uint4 h_, l_;                                                           \
        asm("prmt.b32 %0, %1, %2, 0x7632;" : "=r"(h_.x) : "r"(u0_), "r"(u1_));  \
        asm("prmt.b32 %0, %1, %2, 0x7632;" : "=r"(h_.y) : "r"(u2_), "r"(u3_));  \
        asm("prmt.b32 %0, %1, %2, 0x7632;" : "=r"(h_.z) : "r"(u4_), "r"(u5_));  \
        asm("prmt.b32 %0, %1, %2, 0x7632;" : "=r"(h_.w) : "r"(u6_), "r"(u7_));  \
        float f0_ = va_.x - __uint_as_float(u0_ & 0xFFFF0000u);                 \
        float f1_ = va_.y - __uint_as_float(u1_ & 0xFFFF0000u);                 \
        float f2_ = va_.z - __uint_as_float(u2_ & 0xFFFF0000u);                 \
        float f3_ = va_.w - __uint_as_float(u3_ & 0xFFFF0000u);                 \
        float f4_ = vb_.x - __uint_as_float(u4_ & 0xFFFF0000u);                 \
        float f5_ = vb_.y - __uint_as_float(u5_ & 0xFFFF0000u);                 \
        float f6_ = vb_.z - __uint_as_float(u6_ & 0xFFFF0000u);                 \
        float f7_ = vb_.w - __uint_as_float(u7_ & 0xFFFF0000u);                 \
        asm("cvt.rn.bf16x2.f32 %0, %1, %2;" : "=r"(l_.x) : "f"(f1_), "f"(f0_)); \
        asm("cvt.rn.bf16x2.f32 %0, %1, %2;" : "=r"(l_.y) : "f"(f3_), "f"(f2_)); \
        asm("cvt.rn.bf16x2.f32 %0, %1, %2;" : "=r"(l_.z) : "f"(f5_), "f"(f4_)); \
        asm("cvt.rn.bf16x2.f32 %0, %1, %2;" : "=r"(l_.w) : "f"(f7_), "f"(f6_)); \
        uint32_t c_   = (uint32_t)(aH * 2 + i_);                                \
        uint32_t off_ = (uint32_t)aR * 64 + ((c_ ^ aXor) << 4);                 \
        *reinterpret_cast<uint4*>(sb_ + ST_AH + off_) = h_;                     \
        *reinterpret_cast<uint4*>(sb_ + ST_AL + off_) = l_;                     \
    }                                                                           \
    {                                                                           \
        uint32_t off_ = (uint32_t)bRow * 64 + (((uint32_t)bC ^ bXorS) << 4);    \
        *reinterpret_cast<uint4*>(sb_ + ST_BH + off_) = stBh;                   \
        *reinterpret_cast<uint4*>(sb_ + ST_BL + off_) = stBl;                   \
    }                                                                           \
} while (0)

__global__ __launch_bounds__(GTHREADS, 2) void mma_gemm(const float* __restrict__ A)
{
    __shared__ __align__(128) char sm[S_TOTAL];
    const uint32_t sbase = smem_u32(sm);

    const int tid = threadIdx.x;
    const int wid = tid >> 5;
    const int lid = tid & 31;
    const int wm  = wid * 16;                 // warp's 16-row slice

    const int mBase = blockIdx.x * TM;
    const int kBase = blockIdx.y * KSPAN;
    const float* Ablk = A + (size_t)mBase * N_DIM + kBase;

    // A staging: row aR = tid>>1, half aH = tid&1 (16 floats -> 2 chunks)
    const int aR = tid >> 1;
    const int aH = tid & 1;
    const uint32_t aXor = (uint32_t)((aR >> 1) & 3);
    // B staging: one hi + one lo chunk per thread: row = tid>>2, chunk = tid&3
    const int bRow = tid >> 2;
    const int bC   = tid & 3;
    const uint32_t bXorS = (uint32_t)((bRow >> 1) & 3);

    float4 stA[4];
    uint4  stBh, stBl;

    float acc[8][4];
    #pragma unroll
    for (int t = 0; t < 8; t++)
        #pragma unroll
        for (int j = 0; j < 4; j++) acc[t][j] = 0.0f;

    // per-lane ldmatrix invariants
    //   A x4: rows wm+(lid&15); logical chunk = ks*2 + (lid>>4)
    const uint32_t rA    = (uint32_t)(wm + (lid & 15));
    const uint32_t aFXor = (rA >> 1) & 3u;
    const uint32_t aRowB = rA * 64u;
    const uint32_t aSel  = (uint32_t)(lid >> 4);
    //   B x4: rows np*16 + rBL; logical chunk = ks*2 + bSel
    const uint32_t rBL   = (uint32_t)((lid & 7) + ((lid >> 4) & 1) * 8);
    const uint32_t bFXor = (rBL >> 1) & 3u;   // (rB>>1)&3 == (rBL>>1)&3 (np*16)
    const uint32_t bSel  = (uint32_t)((lid >> 3) & 1);

    // ---- prologue: fill stage 0 ----
    LDG_TILE(0);
    STS_TILE(0);
    __syncthreads();

    for (int it = 0; it < NITER; it++) {
        const uint32_t so = sbase + (uint32_t)(it & 1) * STAGE;

        if (it + 1 < NITER) LDG_TILE(it + 1);   // LDGs fly under compute

        #pragma unroll
        for (int ks = 0; ks < 2; ks++) {
            uint32_t ah[4], al[4];
            {
                uint32_t aOff = (((uint32_t)(ks * 2) + aSel) ^ aFXor) << 4;
                uint32_t aAddr = so + ST_AH + aRowB + aOff;
                ldsm4(ah, aAddr);
                ldsm4(al, aAddr + (ST_AL - ST_AH));
            }
            uint32_t bOff = (((uint32_t)(ks * 2) + bSel) ^ bFXor) << 4;
            #pragma unroll
            for (int np = 0; np < 4; np++) {
                uint32_t bAddr = so + ST_BH + (uint32_t)np * 1024 + rBL * 64 + bOff;
                uint32_t bh[4], bl[4];
                ldsm4(bh, bAddr);
                ldsm4(bl, bAddr + (ST_BL - ST_BH));
                float* c0 = acc[np * 2];
                float* c1 = acc[np * 2 + 1];
                mma16816(c0, ah, bh[0], bh[1]);
                mma16816(c1, ah, bh[2], bh[3]);
                mma16816(c0, ah, bl[0], bl[1]);
                mma16816(c1, ah, bl[2], bl[3]);
                mma16816(c0, al, bh[0], bh[1]);
                mma16816(c1, al, bh[2], bh[3]);
            }
        }

        if (it + 1 < NITER) STS_TILE((it + 1) & 1);  // write other stage
        __syncthreads();                              // single barrier per iter
    }

    // epilogue: c-fragment (row = lid>>2 (+8), col = (lid&3)*2 (+1))
    const int g  = lid >> 2;
    const int tg = lid & 3;
    float* part = g_part + (size_t)blockIdx.y * (N_DIM * OUT_CH);
    const int row0 = mBase + wm + g;
    #pragma unroll
    for (int t = 0; t < 8; t++) {
        int col = t * 8 + tg * 2;
        *reinterpret_cast<float2*>(&part[(size_t)row0 * OUT_CH + col]) =
            make_float2(acc[t][0], acc[t][1]);
        *reinterpret_cast<float2*>(&part[(size_t)(row0 + 8) * OUT_CH + col]) =
            make_float2(acc[t][2], acc[t][3]);
    }
}

// ---------------------------------------------------------------------------
// Kernel 4: reduce split-K partials.
//   phase 0: g_sp = filt[m] * sum_s P[s]     phase 1: d_out = sum_s P[s]
// ---------------------------------------------------------------------------
__global__ __launch_bounds__(256) void reduce_kernel(
    const float* __restrict__ filt, float* __restrict__ outp, int phase)
{
    const int i = blockIdx.x * blockDim.x + threadIdx.x;
    const int stride4 = (N_DIM * OUT_CH) / 4;
    const float4* P = reinterpret_cast<const float4*>(g_part);

    float4 s = P[i];
    #pragma unroll
    for (int sp = 1; sp < SPLITK; sp++) {
        float4 v = P[i + sp * stride4];
        s.x += v.x; s.y += v.y; s.z += v.z; s.w += v.w;
    }
    if (phase == 0) {
        int m = (i * 4) / OUT_CH;
        float f = filt[m];
        s.x *= f; s.y *= f; s.z *= f; s.w *= f;
        reinterpret_cast<float4*>(g_sp)[i] = s;
    } else {
        reinterpret_cast<float4*>(outp)[i] = s;
    }
}

// ---------------------------------------------------------------------------
// Launch. Inputs: features, weight_matrix, filt, wavelets, wavelets_inv.
// No dynamic smem, no attributes, no static state, no device symbols as args.
// ---------------------------------------------------------------------------
extern "C" void kernel_launch(void* const* d_in, const int* in_sizes, int n_in,
                              void* d_out, int out_size)
{
    const float* features     = (const float*)d_in[0];
    const float* weight       = (const float*)d_in[1];
    const float* filt         = (const float*)d_in[2];
    const float* wavelets     = (const float*)d_in[3];
    const float* wavelets_inv = (const float*)d_in[4];
    float* out = (float*)d_out;

    dim3 grid(N_DIM / TM, SPLITK);                      // (64, 8)
    const int prepBlocks = (N_DIM * OUT_CH) / 256;      // 2048
    const int redBlocks  = (N_DIM * OUT_CH) / 4 / 256;  // 512

    // 1) g_tr = features @ W
    lin_kernel<<<N_DIM / 32, 256>>>(features, weight);
    // 2) split+transpose g_tr -> g_bh/g_bl
    prep_b<<<prepBlocks, 256>>>(0);
    // 3) partials = wavelets_inv @ g_tr
    mma_gemm<<<grid, GTHREADS>>>(wavelets_inv);
    // 4) g_sp = filt[:,None] * sum(partials)
    reduce_kernel<<<redBlocks, 256>>>(filt, nullptr, 0);
    // 5) split+transpose g_sp
    prep_b<<<prepBlocks, 256>>>(1);
    // 6) partials = wavelets @ g_sp
    mma_gemm<<<grid, GTHREADS>>>(wavelets);
    // 7) out = sum(partials)
    reduce_kernel<<<redBlocks, 256>>>(filt, out, 1);
}

// round 9
// speedup vs baseline: 1.5030x; 1.1921x over previous
#include <cuda_runtime.h>
#include <cuda_fp16.h>
#include <cstdint>

// ---------------------------------------------------------------------------
// Problem dims
// ---------------------------------------------------------------------------
#define N_DIM  8192
#define IN_CH  128
#define OUT_CH 64

// Big-GEMM tiling (mma.sync fp16 single-term; tcgen05 unavailable here)
#define TM       128               // M rows per CTA
#define KB       32                // K per stage (fp16 elements)
#define SPLITK   8
#define KSPAN    (N_DIM / SPLITK)  // 1024
#define NITER    (KSPAN / KB)      // 32
#define GTHREADS 256               // 8 warps; each warp: 16 rows x 64 cols

// Double-buffered SMEM: 64B rows, chunk swizzle c ^= (r>>1)&3 (16B chunks).
// Stage: A 8192 | B 4096 = 12288 B; x2 = 24576 B.
#define ST_A     0
#define ST_B     8192
#define STAGE    12288
#define S_TOTAL  24576

// ---------------------------------------------------------------------------
// Scratch (__device__ globals). Referenced ONLY from device code — never
// passed as kernel args from host (that was the R4/R5 bug).
// ---------------------------------------------------------------------------
__device__ __align__(16) float g_tr[N_DIM * OUT_CH];             // features @ W
__device__ __align__(16) float g_sp[N_DIM * OUT_CH];             // filt * (Winv @ g_tr)
__device__ __align__(16) float g_part[SPLITK * N_DIM * OUT_CH];  // split-K partials
__device__ __align__(16) __half g_bf[OUT_CH * N_DIM];            // B^T fp16, K-major

// ---------------------------------------------------------------------------
// PTX helpers (baseline ISA: ldmatrix + mma.sync only)
// ---------------------------------------------------------------------------
__device__ __forceinline__ uint32_t smem_u32(const void* p) {
    uint32_t a;
    asm("{ .reg .u64 t; cvta.to.shared.u64 t, %1; cvt.u32.u64 %0, t; }"
        : "=r"(a) : "l"(p));
    return a;
}
__device__ __forceinline__ void ldsm4(uint32_t* r, uint32_t addr) {
    asm volatile("ldmatrix.sync.aligned.m8n8.x4.shared.b16 {%0,%1,%2,%3}, [%4];"
                 : "=r"(r[0]), "=r"(r[1]), "=r"(r[2]), "=r"(r[3]) : "r"(addr));
}
__device__ __forceinline__ void mma16816(float* c, const uint32_t* a,
                                         uint32_t b0, uint32_t b1) {
    asm volatile(
        "mma.sync.aligned.m16n8k16.row.col.f32.f16.f16.f32 "
        "{%0,%1,%2,%3}, {%4,%5,%6,%7}, {%8,%9}, {%0,%1,%2,%3};"
        : "+f"(c[0]), "+f"(c[1]), "+f"(c[2]), "+f"(c[3])
        : "r"(a[0]), "r"(a[1]), "r"(a[2]), "r"(a[3]), "r"(b0), "r"(b1));
}

// ---------------------------------------------------------------------------
// Kernel 1: g_tr = features @ W      [8192,128] @ [128,64]   (R2/R6-proven)
// ---------------------------------------------------------------------------
__global__ __launch_bounds__(256) void lin_kernel(
    const float* __restrict__ F, const float* __restrict__ W)
{
    __shared__ float Ws[IN_CH][OUT_CH];
    const int tid = threadIdx.x;
    #pragma unroll
    for (int t = 0; t < 8; t++) {
        int idx = tid + t * 256;
        int r = idx >> 4, c4 = idx & 15;
        *reinterpret_cast<float4*>(&Ws[r][c4 * 4]) =
            *reinterpret_cast<const float4*>(&W[r * OUT_CH + c4 * 4]);
    }
    __syncthreads();

    const int row = blockIdx.x * 32 + (tid >> 3);
    const int c0  = (tid & 7) * 8;
    float acc[8];
    #pragma unroll
    for (int j = 0; j < 8; j++) acc[j] = 0.0f;

    #pragma unroll 8
    for (int k = 0; k < IN_CH; k += 4) {
        float4 a4 = *reinterpret_cast<const float4*>(&F[row * IN_CH + k]);
        float av[4] = {a4.x, a4.y, a4.z, a4.w};
        #pragma unroll
        for (int kk = 0; kk < 4; kk++)
            #pragma unroll
            for (int j = 0; j < 8; j++)
                acc[j] = fmaf(av[kk], Ws[k + kk][c0 + j], acc[j]);
    }
    #pragma unroll
    for (int j = 0; j < 8; j++) g_tr[row * OUT_CH + c0 + j] = acc[j];
}

// ---------------------------------------------------------------------------
// Kernel 2: transpose src[K,64] fp32 -> K-major fp16 g_bf[64][8192].
//   which=0: src = g_tr ;  which=1: src = g_sp   (selected IN DEVICE CODE)
// ---------------------------------------------------------------------------
__global__ __launch_bounds__(256) void prep_b(int which)
{
    const float* __restrict__ src = which ? g_sp : g_tr;
    int idx = blockIdx.x * 256 + threadIdx.x;       // = n*8192 + k
    int k = idx & (N_DIM - 1);
    int n = idx >> 13;
    g_bf[idx] = __float2half(src[k * OUT_CH + n]);
}

// ---------------------------------------------------------------------------
// Kernel 3: fp16 GEMM (mma.sync.m16n8k16), KB=32, DOUBLE-BUFFERED.
//   partial[s] = A[mTile, kspan_s] @ B^T
// ---------------------------------------------------------------------------

// A: per thread 4 float4 (row aR, 16 floats at col aH*16); B: 1 uint4
#define LDG_TILE(it_) do {                                                      \
    _Pragma("unroll")                                                           \
    for (int j_ = 0; j_ < 4; j_++)                                              \
        stA[j_] = *reinterpret_cast<const float4*>(                             \
            Ablk + (size_t)aR * N_DIM + (it_) * KB + aH * 16 + j_ * 4);         \
    stB = *reinterpret_cast<const uint4*>(                                      \
        g_bf + (size_t)bRow * N_DIM + kBase + (it_) * KB + bC * 8);             \
} while (0)

// Convert fp32 -> fp16, store into stage buf_ (chunk-swizzled 64B rows)
#define STS_TILE(buf_) do {                                                     \
    char* sb_ = sm + (buf_) * STAGE;                                            \
    _Pragma("unroll")                                                           \
    for (int i_ = 0; i_ < 2; i_++) {       /* 16B chunk from 8 floats */        \
        float4 va_ = stA[i_ * 2], vb_ = stA[i_ * 2 + 1];                        \
        uint4 h_;                                                               \
        asm("cvt.rn.f16x2.f32 %0, %1, %2;" : "=r"(h_.x) : "f"(va_.y), "f"(va_.x)); \
        asm("cvt.rn.f16x2.f32 %0, %1, %2;" : "=r"(h_.y) : "f"(va_.w), "f"(va_.z)); \
        asm("cvt.rn.f16x2.f32 %0, %1, %2;" : "=r"(h_.z) : "f"(vb_.y), "f"(vb_.x)); \
        asm("cvt.rn.f16x2.f32 %0, %1, %2;" : "=r"(h_.w) : "f"(vb_.w), "f"(vb_.z)); \
        uint32_t c_   = (uint32_t)(aH * 2 + i_);                                \
        uint32_t off_ = (uint32_t)aR * 64 + ((c_ ^ aXor) << 4);                 \
        *reinterpret_cast<uint4*>(sb_ + ST_A + off_) = h_;                      \
    }                                                                           \
    {                                                                           \
        uint32_t off_ = (uint32_t)bRow * 64 + (((uint32_t)bC ^ bXorS) << 4);    \
        *reinterpret_cast<uint4*>(sb_ + ST_B + off_) = stB;                     \
    }                                                                           \
} while (0)

__global__ __launch_bounds__(GTHREADS, 3) void mma_gemm(const float* __restrict__ A)
{
    __shared__ __align__(128) char sm[S_TOTAL];
    const uint32_t sbase = smem_u32(sm);

    const int tid = threadIdx.x;
    const int wid = tid >> 5;
    const int lid = tid & 31;
    const int wm  = wid * 16;                 // warp's 16-row slice

    const int mBase = blockIdx.x * TM;
    const int kBase = blockIdx.y * KSPAN;
    const float* Ablk = A + (size_t)mBase * N_DIM + kBase;

    // A staging: row aR = tid>>1, half aH = tid&1 (16 floats -> 2 chunks)
    const int aR = tid >> 1;
    const int aH = tid & 1;
    const uint32_t aXor = (uint32_t)((aR >> 1) & 3);
    // B staging: one chunk per thread: row = tid>>2, chunk = tid&3
    const int bRow = tid >> 2;
    const int bC   = tid & 3;
    const uint32_t bXorS = (uint32_t)((bRow >> 1) & 3);

    float4 stA[4];
    uint4  stB;

    float acc[8][4];
    #pragma unroll
    for (int t = 0; t < 8; t++)
        #pragma unroll
        for (int j = 0; j < 4; j++) acc[t][j] = 0.0f;

    // per-lane ldmatrix invariants
    //   A x4: rows wm+(lid&15); logical chunk = ks*2 + (lid>>4)
    const uint32_t rA    = (uint32_t)(wm + (lid & 15));
    const uint32_t aFXor = (rA >> 1) & 3u;
    const uint32_t aRowB = rA * 64u;
    const uint32_t aSel  = (uint32_t)(lid >> 4);
    //   B x4: rows np*16 + rBL; logical chunk = ks*2 + bSel
    const uint32_t rBL   = (uint32_t)((lid & 7) + ((lid >> 4) & 1) * 8);
    const uint32_t bFXor = (rBL >> 1) & 3u;   // np*16 doesn't affect (r>>1)&3
    const uint32_t bSel  = (uint32_t)((lid >> 3) & 1);

    // ---- prologue: fill stage 0 ----
    LDG_TILE(0);
    STS_TILE(0);
    __syncthreads();

    for (int it = 0; it < NITER; it++) {
        const uint32_t so = sbase + (uint32_t)(it & 1) * STAGE;

        if (it + 1 < NITER) LDG_TILE(it + 1);   // LDGs fly under compute

        #pragma unroll
        for (int ks = 0; ks < 2; ks++) {
            uint32_t a[4];
            {
                uint32_t aOff = (((uint32_t)(ks * 2) + aSel) ^ aFXor) << 4;
                ldsm4(a, so + ST_A + aRowB + aOff);
            }
            uint32_t bOff = (((uint32_t)(ks * 2) + bSel) ^ bFXor) << 4;
            #pragma unroll
            for (int np = 0; np < 4; np++) {
                uint32_t bAddr = so + ST_B + (uint32_t)np * 1024 + rBL * 64 + bOff;
                uint32_t b[4];
                ldsm4(b, bAddr);
                mma16816(acc[np * 2],     a, b[0], b[1]);
                mma16816(acc[np * 2 + 1], a, b[2], b[3]);
            }
        }

        if (it + 1 < NITER) STS_TILE((it + 1) & 1);  // write other stage
        __syncthreads();                              // single barrier per iter
    }

    // epilogue: c-fragment (row = lid>>2 (+8), col = (lid&3)*2 (+1))
    const int g  = lid >> 2;
    const int tg = lid & 3;
    float* part = g_part + (size_t)blockIdx.y * (N_DIM * OUT_CH);
    const int row0 = mBase + wm + g;
    #pragma unroll
    for (int t = 0; t < 8; t++) {
        int col = t * 8 + tg * 2;
        *reinterpret_cast<float2*>(&part[(size_t)row0 * OUT_CH + col]) =
            make_float2(acc[t][0], acc[t][1]);
        *reinterpret_cast<float2*>(&part[(size_t)(row0 + 8) * OUT_CH + col]) =
            make_float2(acc[t][2], acc[t][3]);
    }
}

// ---------------------------------------------------------------------------
// Kernel 4: reduce split-K partials.
//   phase 0: g_sp = filt[m] * sum_s P[s]     phase 1: d_out = sum_s P[s]
// ---------------------------------------------------------------------------
__global__ __launch_bounds__(256) void reduce_kernel(
    const float* __restrict__ filt, float* __restrict__ outp, int phase)
{
    const int i = blockIdx.x * blockDim.x + threadIdx.x;
    const int stride4 = (N_DIM * OUT_CH) / 4;
    const float4* P = reinterpret_cast<const float4*>(g_part);

    float4 s = P[i];
    #pragma unroll
    for (int sp = 1; sp < SPLITK; sp++) {
        float4 v = P[i + sp * stride4];
        s.x += v.x; s.y += v.y; s.z += v.z; s.w += v.w;
    }
    if (phase == 0) {
        int m = (i * 4) / OUT_CH;
        float f = filt[m];
        s.x *= f; s.y *= f; s.z *= f; s.w *= f;
        reinterpret_cast<float4*>(g_sp)[i] = s;
    } else {
        reinterpret_cast<float4*>(outp)[i] = s;
    }
}

// ---------------------------------------------------------------------------
// Launch. Inputs: features, weight_matrix, filt, wavelets, wavelets_inv.
// No dynamic smem, no attributes, no static state, no device symbols as args.
// ---------------------------------------------------------------------------
extern "C" void kernel_launch(void* const* d_in, const int* in_sizes, int n_in,
                              void* d_out, int out_size)
{
    const float* features     = (const float*)d_in[0];
    const float* weight       = (const float*)d_in[1];
    const float* filt         = (const float*)d_in[2];
    const float* wavelets     = (const float*)d_in[3];
    const float* wavelets_inv = (const float*)d_in[4];
    float* out = (float*)d_out;

    dim3 grid(N_DIM / TM, SPLITK);                      // (64, 8)
    const int prepBlocks = (N_DIM * OUT_CH) / 256;      // 2048
    const int redBlocks  = (N_DIM * OUT_CH) / 4 / 256;  // 512

    // 1) g_tr = features @ W
    lin_kernel<<<N_DIM / 32, 256>>>(features, weight);
    // 2) transpose g_tr -> g_bf (fp16)
    prep_b<<<prepBlocks, 256>>>(0);
    // 3) partials = wavelets_inv @ g_tr
    mma_gemm<<<grid, GTHREADS>>>(wavelets_inv);
    // 4) g_sp = filt[:,None] * sum(partials)
    reduce_kernel<<<redBlocks, 256>>>(filt, nullptr, 0);
    // 5) transpose g_sp -> g_bf (fp16)
    prep_b<<<prepBlocks, 256>>>(1);
    // 6) partials = wavelets @ g_sp
    mma_gemm<<<grid, GTHREADS>>>(wavelets);
    // 7) out = sum(partials)
    reduce_kernel<<<redBlocks, 256>>>(filt, out, 1);
}

// round 10
// speedup vs baseline: 1.6595x; 1.1041x over previous
#include <cuda_runtime.h>
#include <cuda_fp16.h>
#include <cstdint>

// ---------------------------------------------------------------------------
// Problem dims
// ---------------------------------------------------------------------------
#define N_DIM  8192
#define IN_CH  128
#define OUT_CH 64

// Big-GEMM tiling (mma.sync fp16; tcgen05 unavailable at compute_103)
#define TM       128               // M rows per CTA
#define KB       32                // K per stage (fp16 elements)
#define SPLITK   16
#define KSPAN    (N_DIM / SPLITK)  // 512
#define NITER    (KSPAN / KB)      // 16
#define GTHREADS 256               // 8 warps; each warp: 16 rows x 64 cols

// Double-buffered SMEM: 64B rows, chunk swizzle c ^= (r>>1)&3 (16B chunks).
// Stage: A 8192 | B 4096 = 12288 B; x2 = 24576 B.
#define ST_A     0
#define ST_B     8192
#define STAGE    12288
#define S_TOTAL  24576

// ---------------------------------------------------------------------------
// Scratch (__device__ globals). Referenced ONLY from device code — never
// passed as kernel args from host (that was the R4/R5 bug).
// ---------------------------------------------------------------------------
__device__ __align__(16) float g_part[SPLITK * N_DIM * OUT_CH];  // 32 MB partials
__device__ __align__(16) __half g_bf[OUT_CH * N_DIM];            // B^T fp16, K-major

// ---------------------------------------------------------------------------
// PTX helpers (baseline ISA: ldmatrix + mma.sync only)
// ---------------------------------------------------------------------------
__device__ __forceinline__ uint32_t smem_u32(const void* p) {
    uint32_t a;
    asm("{ .reg .u64 t; cvta.to.shared.u64 t, %1; cvt.u32.u64 %0, t; }"
        : "=r"(a) : "l"(p));
    return a;
}
__device__ __forceinline__ void ldsm4(uint32_t* r, uint32_t addr) {
    asm volatile("ldmatrix.sync.aligned.m8n8.x4.shared.b16 {%0,%1,%2,%3}, [%4];"
                 : "=r"(r[0]), "=r"(r[1]), "=r"(r[2]), "=r"(r[3]) : "r"(addr));
}
__device__ __forceinline__ void mma16816(float* c, const uint32_t* a,
                                         uint32_t b0, uint32_t b1) {
    asm volatile(
        "mma.sync.aligned.m16n8k16.row.col.f32.f16.f16.f32 "
        "{%0,%1,%2,%3}, {%4,%5,%6,%7}, {%8,%9}, {%0,%1,%2,%3};"
        : "+f"(c[0]), "+f"(c[1]), "+f"(c[2]), "+f"(c[3])
        : "r"(a[0]), "r"(a[1]), "r"(a[2]), "r"(a[3]), "r"(b0), "r"(b1));
}

// ---------------------------------------------------------------------------
// Kernel 1: g_bf[n][k] = fp16( (features @ W)[k][n] )   — fused transpose.
// ---------------------------------------------------------------------------
__global__ __launch_bounds__(256) void lin_kernel(
    const float* __restrict__ F, const float* __restrict__ W)
{
    __shared__ float Ws[IN_CH][OUT_CH];
    const int tid = threadIdx.x;
    #pragma unroll
    for (int t = 0; t < 8; t++) {
        int idx = tid + t * 256;
        int r = idx >> 4, c4 = idx & 15;
        *reinterpret_cast<float4*>(&Ws[r][c4 * 4]) =
            *reinterpret_cast<const float4*>(&W[r * OUT_CH + c4 * 4]);
    }
    __syncthreads();

    const int row = blockIdx.x * 32 + (tid >> 3);   // k index (0..8191)
    const int c0  = (tid & 7) * 8;                  // n base
    float acc[8];
    #pragma unroll
    for (int j = 0; j < 8; j++) acc[j] = 0.0f;

    #pragma unroll 8
    for (int k = 0; k < IN_CH; k += 4) {
        float4 a4 = *reinterpret_cast<const float4*>(&F[row * IN_CH + k]);
        float av[4] = {a4.x, a4.y, a4.z, a4.w};
        #pragma unroll
        for (int kk = 0; kk < 4; kk++)
            #pragma unroll
            for (int j = 0; j < 8; j++)
                acc[j] = fmaf(av[kk], Ws[k + kk][c0 + j], acc[j]);
    }
    // transposed fp16 store: g_bf[(c0+j) * N_DIM + row]
    #pragma unroll
    for (int j = 0; j < 8; j++)
        g_bf[(size_t)(c0 + j) * N_DIM + row] = __float2half(acc[j]);
}

// ---------------------------------------------------------------------------
// Kernel 2: fp16 GEMM (mma.sync.m16n8k16), KB=32, DOUBLE-BUFFERED.
//   partial[s] = A[mTile, kspan_s] @ B^T      (B from g_bf)
// ---------------------------------------------------------------------------

// A: per thread 4 float4 (row aR, 16 floats at col aH*16); B: 1 uint4
#define LDG_TILE(it_) do {                                                      \
    _Pragma("unroll")                                                           \
    for (int j_ = 0; j_ < 4; j_++)                                              \
        stA[j_] = *reinterpret_cast<const float4*>(                             \
            Ablk + (size_t)aR * N_DIM + (it_) * KB + aH * 16 + j_ * 4);         \
    stB = *reinterpret_cast<const uint4*>(                                      \
        g_bf + (size_t)bRow * N_DIM + kBase + (it_) * KB + bC * 8);             \
} while (0)

// Convert fp32 -> fp16, store into stage buf_ (chunk-swizzled 64B rows)
#define STS_TILE(buf_) do {                                                     \
    char* sb_ = sm + (buf_) * STAGE;                                            \
    _Pragma("unroll")                                                           \
    for (int i_ = 0; i_ < 2; i_++) {       /* 16B chunk from 8 floats */        \
        float4 va_ = stA[i_ * 2], vb_ = stA[i_ * 2 + 1];                        \
        uint4 h_;                                                               \
        asm("cvt.rn.f16x2.f32 %0, %1, %2;" : "=r"(h_.x) : "f"(va_.y), "f"(va_.x)); \
        asm("cvt.rn.f16x2.f32 %0, %1, %2;" : "=r"(h_.y) : "f"(va_.w), "f"(va_.z)); \
        asm("cvt.rn.f16x2.f32 %0, %1, %2;" : "=r"(h_.z) : "f"(vb_.y), "f"(vb_.x)); \
        asm("cvt.rn.f16x2.f32 %0, %1, %2;" : "=r"(h_.w) : "f"(vb_.w), "f"(vb_.z)); \
        uint32_t c_   = (uint32_t)(aH * 2 + i_);                                \
        uint32_t off_ = (uint32_t)aR * 64 + ((c_ ^ aXor) << 4);                 \
        *reinterpret_cast<uint4*>(sb_ + ST_A + off_) = h_;                      \
    }                                                                           \
    {                                                                           \
        uint32_t off_ = (uint32_t)bRow * 64 + (((uint32_t)bC ^ bXorS) << 4);    \
        *reinterpret_cast<uint4*>(sb_ + ST_B + off_) = stB;                     \
    }                                                                           \
} while (0)

__global__ __launch_bounds__(GTHREADS, 3) void mma_gemm(const float* __restrict__ A)
{
    __shared__ __align__(128) char sm[S_TOTAL];
    const uint32_t sbase = smem_u32(sm);

    const int tid = threadIdx.x;
    const int wid = tid >> 5;
    const int lid = tid & 31;
    const int wm  = wid * 16;                 // warp's 16-row slice

    const int mBase = blockIdx.x * TM;
    const int kBase = blockIdx.y * KSPAN;
    const float* Ablk = A + (size_t)mBase * N_DIM + kBase;

    // A staging: row aR = tid>>1, half aH = tid&1 (16 floats -> 2 chunks)
    const int aR = tid >> 1;
    const int aH = tid & 1;
    const uint32_t aXor = (uint32_t)((aR >> 1) & 3);
    // B staging: one chunk per thread: row = tid>>2, chunk = tid&3
    const int bRow = tid >> 2;
    const int bC   = tid & 3;
    const uint32_t bXorS = (uint32_t)((bRow >> 1) & 3);

    float4 stA[4];
    uint4  stB;

    float acc[8][4];
    #pragma unroll
    for (int t = 0; t < 8; t++)
        #pragma unroll
        for (int j = 0; j < 4; j++) acc[t][j] = 0.0f;

    // per-lane ldmatrix invariants
    const uint32_t rA    = (uint32_t)(wm + (lid & 15));
    const uint32_t aFXor = (rA >> 1) & 3u;
    const uint32_t aRowB = rA * 64u;
    const uint32_t aSel  = (uint32_t)(lid >> 4);
    const uint32_t rBL   = (uint32_t)((lid & 7) + ((lid >> 4) & 1) * 8);
    const uint32_t bFXor = (rBL >> 1) & 3u;
    const uint32_t bSel  = (uint32_t)((lid >> 3) & 1);

    // ---- prologue: fill stage 0 ----
    LDG_TILE(0);
    STS_TILE(0);
    __syncthreads();

    for (int it = 0; it < NITER; it++) {
        const uint32_t so = sbase + (uint32_t)(it & 1) * STAGE;

        if (it + 1 < NITER) LDG_TILE(it + 1);   // LDGs fly under compute

        #pragma unroll
        for (int ks = 0; ks < 2; ks++) {
            uint32_t a[4];
            {
                uint32_t aOff = (((uint32_t)(ks * 2) + aSel) ^ aFXor) << 4;
                ldsm4(a, so + ST_A + aRowB + aOff);
            }
            uint32_t bOff = (((uint32_t)(ks * 2) + bSel) ^ bFXor) << 4;
            #pragma unroll
            for (int np = 0; np < 4; np++) {
                uint32_t bAddr = so + ST_B + (uint32_t)np * 1024 + rBL * 64 + bOff;
                uint32_t b[4];
                ldsm4(b, bAddr);
                mma16816(acc[np * 2],     a, b[0], b[1]);
                mma16816(acc[np * 2 + 1], a, b[2], b[3]);
            }
        }

        if (it + 1 < NITER) STS_TILE((it + 1) & 1);  // write other stage
        __syncthreads();                              // single barrier per iter
    }

    // epilogue: c-fragment (row = lid>>2 (+8), col = (lid&3)*2 (+1))
    const int g  = lid >> 2;
    const int tg = lid & 3;
    float* part = g_part + (size_t)blockIdx.y * (N_DIM * OUT_CH);
    const int row0 = mBase + wm + g;
    #pragma unroll
    for (int t = 0; t < 8; t++) {
        int col = t * 8 + tg * 2;
        *reinterpret_cast<float2*>(&part[(size_t)row0 * OUT_CH + col]) =
            make_float2(acc[t][0], acc[t][1]);
        *reinterpret_cast<float2*>(&part[(size_t)(row0 + 8) * OUT_CH + col]) =
            make_float2(acc[t][2], acc[t][3]);
    }
}

// ---------------------------------------------------------------------------
// Kernel 3: reduce split-K partials.
//   phase 0: g_bf[n][m] = fp16( filt[m] * sum_s P[s][m][n] )  (fused transpose)
//   phase 1: d_out      = sum_s P[s]
// ---------------------------------------------------------------------------
__global__ __launch_bounds__(256) void reduce_kernel(
    const float* __restrict__ filt, float* __restrict__ outp, int phase)
{
    const int i = blockIdx.x * blockDim.x + threadIdx.x;  // float4 index
    const int stride4 = (N_DIM * OUT_CH) / 4;
    const float4* P = reinterpret_cast<const float4*>(g_part);

    float4 s = P[i];
    #pragma unroll
    for (int sp = 1; sp < SPLITK; sp++) {
        float4 v = P[i + sp * stride4];
        s.x += v.x; s.y += v.y; s.z += v.z; s.w += v.w;
    }
    if (phase == 0) {
        int m = (i * 4) / OUT_CH;     // OUT_CH % 4 == 0 -> constant per float4
        int c = (i * 4) % OUT_CH;
        float f = filt[m];
        g_bf[(size_t)(c + 0) * N_DIM + m] = __float2half(s.x * f);
        g_bf[(size_t)(c + 1) * N_DIM + m] = __float2half(s.y * f);
        g_bf[(size_t)(c + 2) * N_DIM + m] = __float2half(s.z * f);
        g_bf[(size_t)(c + 3) * N_DIM + m] = __float2half(s.w * f);
    } else {
        reinterpret_cast<float4*>(outp)[i] = s;
    }
}

// ---------------------------------------------------------------------------
// Launch. Inputs: features, weight_matrix, filt, wavelets, wavelets_inv.
// No dynamic smem, no attributes, no static state, no device symbols as args.
// ---------------------------------------------------------------------------
extern "C" void kernel_launch(void* const* d_in, const int* in_sizes, int n_in,
                              void* d_out, int out_size)
{
    const float* features     = (const float*)d_in[0];
    const float* weight       = (const float*)d_in[1];
    const float* filt         = (const float*)d_in[2];
    const float* wavelets     = (const float*)d_in[3];
    const float* wavelets_inv = (const float*)d_in[4];
    float* out = (float*)d_out;

    dim3 grid(N_DIM / TM, SPLITK);                      // (64, 16)
    const int redBlocks = (N_DIM * OUT_CH) / 4 / 256;   // 512

    // 1) g_bf = (features @ W)^T as fp16   (fused linear + transpose)
    lin_kernel<<<N_DIM / 32, 256>>>(features, weight);
    // 2) partials = wavelets_inv @ g_bf^T
    mma_gemm<<<grid, GTHREADS>>>(wavelets_inv);
    // 3) g_bf = (filt[:,None] * sum(partials))^T as fp16  (fused reduce)
    reduce_kernel<<<redBlocks, 256>>>(filt, nullptr, 0);
    // 4) partials = wavelets @ g_bf^T
    mma_gemm<<<grid, GTHREADS>>>(wavelets);
    // 5) out = sum(partials)
    reduce_kernel<<<redBlocks, 256>>>(filt, out, 1);
}